// round 13
// baseline (speedup 1.0000x reference)
#include <cuda_runtime.h>
#include <cuda_fp16.h>
#include <cstdint>

#define N_B 32
#define T_S 2048
#define D_E 1024
#define U_D 1024

// Scratch (device globals: no allocation allowed)
__device__ float g_pq[2 * N_B * U_D];      // proj_query partials (k halves)
__device__ float g_weights[N_B * T_S];     // logits     [32,2048]
__device__ __half g_wkH[U_D * D_E];        // Wk hi fp16 (2MB)
__device__ __half g_wkL[U_D * D_E];        // Wk lo fp16 (2MB)

// ===========================================================================
// Helpers
// ===========================================================================
__device__ __forceinline__ uint32_t smem_u32(const void* p) {
    uint32_t a;
    asm("{ .reg .u64 t; cvta.to.shared.u64 t, %1; cvt.u32.u64 %0, t; }"
        : "=r"(a) : "l"(p));
    return a;
}
__device__ __forceinline__ void ldm4(uint32_t* r, uint32_t addr) {
    asm volatile("ldmatrix.sync.aligned.m8n8.x4.shared.b16 {%0,%1,%2,%3}, [%4];"
                 : "=r"(r[0]), "=r"(r[1]), "=r"(r[2]), "=r"(r[3]) : "r"(addr));
}
__device__ __forceinline__ void mma16816(float* c, const uint32_t* a,
                                         const uint32_t* b) {
    asm volatile(
        "mma.sync.aligned.m16n8k16.row.col.f32.f16.f16.f32 "
        "{%0,%1,%2,%3}, {%4,%5,%6,%7}, {%8,%9}, {%0,%1,%2,%3};"
        : "+f"(c[0]), "+f"(c[1]), "+f"(c[2]), "+f"(c[3])
        : "r"(a[0]), "r"(a[1]), "r"(a[2]), "r"(a[3]), "r"(b[0]), "r"(b[1]));
}
__device__ __forceinline__ void cpasync16(uint32_t dst, const void* src) {
    asm volatile("cp.async.cg.shared.global [%0], [%1], 16;"
                 :: "r"(dst), "l"(src) : "memory");
}
__device__ __forceinline__ void cp_commit() {
    asm volatile("cp.async.commit_group;" ::: "memory");
}
__device__ __forceinline__ float tanh_fast(float x) {
    float y;
    asm("tanh.approx.f32 %0, %1;" : "=f"(y) : "f"(x));
    return y;
}
__device__ __forceinline__ void sts128(uint32_t addr, uint4 u) {
    asm volatile("st.shared.v4.b32 [%0], {%1,%2,%3,%4};"
                 :: "r"(addr), "r"(u.x), "r"(u.y), "r"(u.z), "r"(u.w) : "memory");
}
__device__ __forceinline__ void split8(const float4 f0, const float4 f1,
                                       uint4& hi, uint4& lo) {
    __half2 h0 = __floats2half2_rn(f0.x, f0.y);
    __half2 h1 = __floats2half2_rn(f0.z, f0.w);
    __half2 h2 = __floats2half2_rn(f1.x, f1.y);
    __half2 h3 = __floats2half2_rn(f1.z, f1.w);
    float2 a0 = __half22float2(h0), a1 = __half22float2(h1);
    float2 a2 = __half22float2(h2), a3 = __half22float2(h3);
    __half2 l0 = __floats2half2_rn(f0.x - a0.x, f0.y - a0.y);
    __half2 l1 = __floats2half2_rn(f0.z - a1.x, f0.w - a1.y);
    __half2 l2 = __floats2half2_rn(f1.x - a2.x, f1.y - a2.y);
    __half2 l3 = __floats2half2_rn(f1.z - a3.x, f1.w - a3.y);
    hi = make_uint4(*(uint32_t*)&h0, *(uint32_t*)&h1, *(uint32_t*)&h2, *(uint32_t*)&h3);
    lo = make_uint4(*(uint32_t*)&l0, *(uint32_t*)&l1, *(uint32_t*)&l2, *(uint32_t*)&l3);
}

// ===========================================================================
// Fused prep kernel: pq | convert_wk | zero   (enc conversion is gone)
//   [0, 256)     pq
//   [256, 768)   convert_wk
//   [768, 864)   zero g_weights + ctx
// ===========================================================================
#define PREP_WK0    256
#define PREP_ZERO0  768
#define PREP_NBLK   864

__global__ void __launch_bounds__(256)
prep_kernel(const float* __restrict__ q, const float* __restrict__ Wq,
            const float* __restrict__ Wk, float* __restrict__ ctx) {
    __shared__ float q_s[N_B][128];
    int bid = blockIdx.x;
    int tid = threadIdx.x;

    if (bid < PREP_WK0) {
        int half = bid & 1;
        int u    = (bid >> 1) * 8 + (tid >> 5);
        int lane = tid & 31;
        int k0   = half * 512;

        float acc[N_B];
        #pragma unroll
        for (int n = 0; n < N_B; n++) acc[n] = 0.f;

        for (int kc = 0; kc < 4; kc++) {
            __syncthreads();
            #pragma unroll
            for (int i = 0; i < 4; i++) {
                int flat4 = tid + i * 256;
                int n   = flat4 >> 5;
                int col = (flat4 & 31) * 4;
                *(float4*)&q_s[n][col] =
                    *(const float4*)(q + (size_t)n * D_E + k0 + kc * 128 + col);
            }
            __syncthreads();
            float4 w = *(const float4*)(Wq + (size_t)u * D_E + k0 + kc * 128 + lane * 4);
            #pragma unroll
            for (int n = 0; n < N_B; n++) {
                float4 qv = *(const float4*)&q_s[n][lane * 4];
                acc[n] += qv.x * w.x + qv.y * w.y + qv.z * w.z + qv.w * w.w;
            }
        }
        #pragma unroll
        for (int n = 0; n < N_B; n++) {
            float s = acc[n];
            #pragma unroll
            for (int o = 16; o > 0; o >>= 1) s += __shfl_down_sync(0xffffffffu, s, o);
            if (lane == 0) g_pq[half * N_B * U_D + n * U_D + u] = s;
        }
    } else if (bid < PREP_ZERO0) {
        size_t base = ((size_t)(bid - PREP_WK0) * 256 + tid) * 8;
        float4 f0 = *(const float4*)(Wk + base);
        float4 f1 = *(const float4*)(Wk + base + 4);
        uint4 hi, lo;
        split8(f0, f1, hi, lo);
        *(uint4*)(g_wkH + base) = hi;
        *(uint4*)(g_wkL + base) = lo;
    } else {
        int flat = (bid - PREP_ZERO0) * 256 + tid;   // < 24576
        if (flat < 16384)
            *(float4*)(g_weights + (size_t)flat * 4) = make_float4(0, 0, 0, 0);
        else
            *(float4*)(ctx + (size_t)(flat - 16384) * 4) = make_float4(0, 0, 0, 0);
    }
}

// ===========================================================================
// Fused softmax + context (unchanged from R12)
// ===========================================================================
__global__ void __launch_bounds__(256)
sm_context_kernel(const float* __restrict__ enc,
                  const int* __restrict__ lengths,
                  float* __restrict__ align, float* __restrict__ ctx) {
    int n    = blockIdx.y;
    int len  = lengths[n];
    int tc   = blockIdx.z * 128;
    bool wr  = (blockIdx.x == 0);
    if (!wr && tc >= len) return;

    int tid = threadIdx.x;
    const float* w = g_weights + (size_t)n * T_S;
    __shared__ float sm[256];

    float m = -1e30f;
    for (int t = tid; t < len; t += 256) m = fmaxf(m, w[t]);
    sm[tid] = m; __syncthreads();
    #pragma unroll
    for (int s = 128; s > 0; s >>= 1) {
        if (tid < s) sm[tid] = fmaxf(sm[tid], sm[tid + s]);
        __syncthreads();
    }
    m = sm[0]; __syncthreads();

    float sum = 0.f;
    for (int t = tid; t < len; t += 256) sum += __expf(w[t] - m);
    sm[tid] = sum; __syncthreads();
    #pragma unroll
    for (int s = 128; s > 0; s >>= 1) {
        if (tid < s) sm[tid] += sm[tid + s];
        __syncthreads();
    }
    float inv = 1.f / sm[0];

    if (wr) {
        if (tid < 128) {
            int t = tc + tid;
            align[(size_t)n * T_S + t] = (t < len) ? __expf(w[t] - m) * inv : 0.f;
        }
        if (tc >= len) return;
    }

    int te = min(tc + 128, len);
    int e  = blockIdx.x * 256 + tid;
    const float* E = enc + ((size_t)n * T_S) * D_E + e;

    float a[8];
    float c0 = 0.f, c1 = 0.f, c2 = 0.f, c3 = 0.f;
    float c4 = 0.f, c5 = 0.f, c6 = 0.f, c7 = 0.f;
    int t = tc;
    for (; t + 8 <= te; t += 8) {
        #pragma unroll
        for (int j = 0; j < 8; j++) a[j] = __expf(w[t + j] - m) * inv;
        c0 += a[0] * E[(size_t)(t + 0) * D_E];
        c1 += a[1] * E[(size_t)(t + 1) * D_E];
        c2 += a[2] * E[(size_t)(t + 2) * D_E];
        c3 += a[3] * E[(size_t)(t + 3) * D_E];
        c4 += a[4] * E[(size_t)(t + 4) * D_E];
        c5 += a[5] * E[(size_t)(t + 5) * D_E];
        c6 += a[6] * E[(size_t)(t + 6) * D_E];
        c7 += a[7] * E[(size_t)(t + 7) * D_E];
    }
    for (; t < te; t++) c0 += __expf(w[t] - m) * inv * E[(size_t)t * D_E];
    float tot = ((c0 + c1) + (c2 + c3)) + ((c4 + c5) + (c6 + c7));
    atomicAdd(&ctx[(size_t)n * D_E + e], tot);
}

// ===========================================================================
// mma.sync 3xFP16-split fused logits GEMM
//   A (enc) loaded fp32, split hi/lo in-loop; B halves precomputed+cp.async.
//   hi fragments double-buffered (cross-barrier prefetch); lo single-buffered.
// ===========================================================================
#define BKF     64                    // fp32 K elems per chunk
#define NKC     (D_E / BKF)           // 16 chunks
#define OFF_AH  0
#define OFF_AL  16384
#define OFF_BH  32768
#define OFF_BL  49152
#define STAGE_B 65536
#define NST     3
#define DYN_SMEM (NST * STAGE_B)

__global__ void __launch_bounds__(512, 1)
weights_tc_kernel(const float* __restrict__ enc, const float* __restrict__ v,
                  const int* __restrict__ lengths) {
    int n  = blockIdx.z;
    int t0 = blockIdx.y * 128;
    int u0 = blockIdx.x * 128;
    int len = lengths[n];
    if (t0 >= len) return;

    extern __shared__ char dyn_smem[];
    __shared__ float wpart[128];
    uint32_t base = smem_u32(dyn_smem);

    int tid  = threadIdx.x;
    int wid  = tid >> 5;
    int lane = tid & 31;
    int mr0 = (wid >> 2) * 32;
    int nc0 = (wid & 3) * 32;

    int rA  = lane & 15;
    int kgA = lane >> 4;
    int swA = rA & 7;
    int rB  = (lane & 7) | ((lane >> 4) << 3);
    int kgB = (lane >> 3) & 1;
    int swB = rB & 7;
    uint32_t rowA = (uint32_t)(mr0 + rA) * 128;
    uint32_t rowB = (uint32_t)(nc0 + rB) * 128;

    // loader geometry: row = tid>>2 (128 rows), element groups g0,g0+1 (8 elems each)
    int arow = tid >> 2;
    int g0   = (tid & 3) * 2;
    const float*  srcA  = enc + ((size_t)n * T_S + t0 + arow) * D_E + g0 * 8;
    const __half* srcBH = g_wkH + ((size_t)(u0 + arow)) * D_E + g0 * 8;
    const __half* srcBL = g_wkL + ((size_t)(u0 + arow)) * D_E + g0 * 8;
    uint32_t d0 = base + (uint32_t)arow * 128 + (uint32_t)((g0 ^ (arow & 7)) << 4);
    uint32_t d1 = base + (uint32_t)arow * 128 + (uint32_t)(((g0 + 1) ^ (arow & 7)) << 4);

    float c[2][4][4];
    #pragma unroll
    for (int mi = 0; mi < 2; mi++)
        #pragma unroll
        for (int ni = 0; ni < 4; ni++)
            #pragma unroll
            for (int k = 0; k < 4; k++) c[mi][ni][k] = 0.f;

    // hi frags double-buffered; lo frags single-buffered
    uint32_t ah[2][2][4], bh[2][8], al[2][4], bl[8];
    float4 fa[4];   // fp32 A staging for next chunk

#define CP_B(stg, kchunk) do {                                               \
        uint32_t _st = (uint32_t)(stg) * STAGE_B;                            \
        size_t _ko = (size_t)(kchunk) * BKF;                                 \
        cpasync16(d0 + _st + OFF_BH, srcBH + _ko);                           \
        cpasync16(d1 + _st + OFF_BH, srcBH + _ko + 8);                       \
        cpasync16(d0 + _st + OFF_BL, srcBL + _ko);                           \
        cpasync16(d1 + _st + OFF_BL, srcBL + _ko + 8);                       \
        cp_commit();                                                         \
    } while (0)

#define LDG_A(kchunk) do {                                                   \
        const float* _g = srcA + (size_t)(kchunk) * BKF;                     \
        fa[0] = *(const float4*)(_g);                                        \
        fa[1] = *(const float4*)(_g + 4);                                    \
        fa[2] = *(const float4*)(_g + 8);                                    \
        fa[3] = *(const float4*)(_g + 12);                                   \
    } while (0)

#define STS_A(stg) do {                                                      \
        uint32_t _st = (uint32_t)(stg) * STAGE_B;                            \
        uint4 _h, _l;                                                        \
        split8(fa[0], fa[1], _h, _l);                                        \
        sts128(d0 + _st + OFF_AH, _h);                                       \
        sts128(d0 + _st + OFF_AL, _l);                                       \
        split8(fa[2], fa[3], _h, _l);                                        \
        sts128(d1 + _st + OFF_AH, _h);                                       \
        sts128(d1 + _st + OFF_AL, _l);                                       \
    } while (0)

#define LOAD_HI(buf, stg, ks) do {                                           \
        uint32_t _sb = base + (uint32_t)(stg) * STAGE_B;                     \
        uint32_t _gA = (uint32_t)((((ks) * 2 + kgA) ^ swA) << 4);            \
        uint32_t _gB = (uint32_t)((((ks) * 2 + kgB) ^ swB) << 4);            \
        uint32_t _aAH = _sb + OFF_AH + rowA;                                 \
        uint32_t _aBH = _sb + OFF_BH + rowB;                                 \
        ldm4(ah[buf][0], _aAH + _gA);                                        \
        ldm4(ah[buf][1], _aAH + 2048 + _gA);                                 \
        ldm4(bh[buf] + 0, _aBH + _gB);                                       \
        ldm4(bh[buf] + 4, _aBH + 2048 + _gB);                                \
    } while (0)

#define LOAD_LO(stg, ks) do {                                                \
        uint32_t _sb = base + (uint32_t)(stg) * STAGE_B;                     \
        uint32_t _gA = (uint32_t)((((ks) * 2 + kgA) ^ swA) << 4);            \
        uint32_t _gB = (uint32_t)((((ks) * 2 + kgB) ^ swB) << 4);            \
        uint32_t _aAL = _sb + OFF_AL + rowA;                                 \
        uint32_t _aBL = _sb + OFF_BL + rowB;                                 \
        ldm4(al[0], _aAL + _gA);                                             \
        ldm4(al[1], _aAL + 2048 + _gA);                                      \
        ldm4(bl + 0, _aBL + _gB);                                            \
        ldm4(bl + 4, _aBL + 2048 + _gB);                                     \
    } while (0)

#define MMA_HI(buf) do {                                                     \
        _Pragma("unroll")                                                    \
        for (int mi = 0; mi < 2; mi++)                                       \
            _Pragma("unroll")                                                \
            for (int ni = 0; ni < 4; ni++)                                   \
                mma16816(c[mi][ni], ah[buf][mi], bh[buf] + ni * 2);          \
    } while (0)

#define MMA_CROSS(buf) do {                                                  \
        _Pragma("unroll")                                                    \
        for (int mi = 0; mi < 2; mi++)                                       \
            _Pragma("unroll")                                                \
            for (int ni = 0; ni < 4; ni++) {                                 \
                mma16816(c[mi][ni], ah[buf][mi], bl + ni * 2);               \
                mma16816(c[mi][ni], al[mi], bh[buf] + ni * 2);               \
            }                                                                \
    } while (0)

    // ---- prologue ----
    CP_B(0, 0);
    CP_B(1, 1);
    LDG_A(0);
    STS_A(0);
    LDG_A(1);
    asm volatile("cp.async.wait_group 1;" ::: "memory");
    __syncthreads();
    LOAD_HI(0, 0, 0);

    for (int kc = 0; kc < NKC; kc++) {
        int stg = kc % NST;
        if (kc + 2 < NKC)
            CP_B((kc + 2) % NST, kc + 2);

        // ks0
        LOAD_LO(stg, 0);
        MMA_HI(0);
        LOAD_HI(1, stg, 1);
        MMA_CROSS(0);
        if (kc + 1 < NKC)
            STS_A((kc + 1) % NST);

        // ks1
        LOAD_LO(stg, 1);
        MMA_HI(1);
        LOAD_HI(0, stg, 2);
        MMA_CROSS(1);
        if (kc + 2 < NKC)
            LDG_A(kc + 2);

        // ks2
        LOAD_LO(stg, 2);
        MMA_HI(0);
        LOAD_HI(1, stg, 3);
        MMA_CROSS(0);

        // ks3
        LOAD_LO(stg, 3);
        MMA_HI(1);
        if (kc + 1 < NKC) {
            asm volatile("cp.async.wait_group 1;" ::: "memory");
            __syncthreads();
            LOAD_HI(0, (kc + 1) % NST, 0);
        }
        MMA_CROSS(1);
    }

    // ---- fused epilogue (HW tanh.approx; pq = sum of two k-half partials) ----
    if (tid < 128) wpart[tid] = 0.f;
    __syncthreads();

    float vv[4][2], pqv[4][2];
    {
        const float* pqp = g_pq + (size_t)n * U_D + u0 + nc0;
        const float* vp  = v + u0 + nc0;
        #pragma unroll
        for (int ni = 0; ni < 4; ni++) {
            int cb = ni * 8 + 2 * (lane & 3);
            vv[ni][0] = vp[cb];     vv[ni][1] = vp[cb + 1];
            pqv[ni][0] = pqp[cb] + pqp[N_B * U_D + cb];
            pqv[ni][1] = pqp[cb + 1] + pqp[N_B * U_D + cb + 1];
        }
    }
    #pragma unroll
    for (int mi = 0; mi < 2; mi++) {
        float s1 = 0.f, s2 = 0.f;
        #pragma unroll
        for (int ni = 0; ni < 4; ni++) {
            s1 += vv[ni][0] * tanh_fast(c[mi][ni][0] + pqv[ni][0]);
            s1 += vv[ni][1] * tanh_fast(c[mi][ni][1] + pqv[ni][1]);
            s2 += vv[ni][0] * tanh_fast(c[mi][ni][2] + pqv[ni][0]);
            s2 += vv[ni][1] * tanh_fast(c[mi][ni][3] + pqv[ni][1]);
        }
        s1 += __shfl_xor_sync(0xffffffffu, s1, 1);
        s1 += __shfl_xor_sync(0xffffffffu, s1, 2);
        s2 += __shfl_xor_sync(0xffffffffu, s2, 1);
        s2 += __shfl_xor_sync(0xffffffffu, s2, 2);
        if ((lane & 3) == 0) {
            int r1 = mr0 + mi * 16 + (lane >> 2);
            atomicAdd(&wpart[r1], s1);
            atomicAdd(&wpart[r1 + 8], s2);
        }
    }
    __syncthreads();
    if (tid < 128 && (t0 + tid) < len)
        atomicAdd(&g_weights[n * T_S + t0 + tid], wpart[tid]);
}

// ===========================================================================
extern "C" void kernel_launch(void* const* d_in, const int* in_sizes, int n_in,
                              void* d_out, int out_size) {
    const float* q       = (const float*)d_in[0];  // [32,1,1024]
    const float* enc     = (const float*)d_in[1];  // [32,2048,1024]
    const int*   lengths = (const int*)  d_in[2];  // [32]
    const float* v       = (const float*)d_in[3];  // [1024]
    const float* Wq      = (const float*)d_in[4];  // [1024,1024]
    const float* Wk      = (const float*)d_in[5];  // [1024,1024]

    float* out   = (float*)d_out;
    float* ctx   = out;                 // contexts   [32,1024]
    float* align = out + N_B * D_E;     // alignments [32,2048]

    cudaFuncSetAttribute(weights_tc_kernel,
                         cudaFuncAttributeMaxDynamicSharedMemorySize, DYN_SMEM);

    prep_kernel<<<PREP_NBLK, 256>>>(q, Wq, Wk, ctx);

    dim3 g(U_D / 128, T_S / 128, N_B);   // u fastest for L2 reuse of enc tiles
    weights_tc_kernel<<<g, 512, DYN_SMEM>>>(enc, v, lengths);

    dim3 gc(D_E / 256, N_B, T_S / 128);
    sm_context_kernel<<<gc, 256>>>(enc, lengths, align, ctx);
}

// round 14
// speedup vs baseline: 1.0278x; 1.0278x over previous
#include <cuda_runtime.h>
#include <cuda_fp16.h>
#include <cstdint>

#define N_B 32
#define T_S 2048
#define D_E 1024
#define U_D 1024

// Scratch (device globals: no allocation allowed)
__device__ float g_pq[2 * N_B * U_D];      // proj_query partials (k halves)
__device__ float g_weights[N_B * T_S];     // logits     [32,2048]
__device__ __half g_encH[N_B * T_S * D_E]; // enc hi fp16 (128MB)
__device__ __half g_encL[N_B * T_S * D_E]; // enc lo fp16 (128MB)
__device__ __half g_wkH[U_D * D_E];        // Wk hi fp16 (2MB)
__device__ __half g_wkL[U_D * D_E];        // Wk lo fp16 (2MB)

// ===========================================================================
// Helpers
// ===========================================================================
__device__ __forceinline__ uint32_t smem_u32(const void* p) {
    uint32_t a;
    asm("{ .reg .u64 t; cvta.to.shared.u64 t, %1; cvt.u32.u64 %0, t; }"
        : "=r"(a) : "l"(p));
    return a;
}
__device__ __forceinline__ void ldm4(uint32_t* r, uint32_t addr) {
    asm volatile("ldmatrix.sync.aligned.m8n8.x4.shared.b16 {%0,%1,%2,%3}, [%4];"
                 : "=r"(r[0]), "=r"(r[1]), "=r"(r[2]), "=r"(r[3]) : "r"(addr));
}
__device__ __forceinline__ void mma16816(float* c, const uint32_t* a,
                                         const uint32_t* b) {
    asm volatile(
        "mma.sync.aligned.m16n8k16.row.col.f32.f16.f16.f32 "
        "{%0,%1,%2,%3}, {%4,%5,%6,%7}, {%8,%9}, {%0,%1,%2,%3};"
        : "+f"(c[0]), "+f"(c[1]), "+f"(c[2]), "+f"(c[3])
        : "r"(a[0]), "r"(a[1]), "r"(a[2]), "r"(a[3]), "r"(b[0]), "r"(b[1]));
}
__device__ __forceinline__ void cpasync16(uint32_t dst, const void* src) {
    asm volatile("cp.async.cg.shared.global [%0], [%1], 16;"
                 :: "r"(dst), "l"(src) : "memory");
}
__device__ __forceinline__ void cp_commit() {
    asm volatile("cp.async.commit_group;" ::: "memory");
}
__device__ __forceinline__ float tanh_fast(float x) {
    float y;
    asm("tanh.approx.f32 %0, %1;" : "=f"(y) : "f"(x));
    return y;
}
__device__ __forceinline__ void split8(const float4 f0, const float4 f1,
                                       uint4& hi, uint4& lo) {
    __half2 h0 = __floats2half2_rn(f0.x, f0.y);
    __half2 h1 = __floats2half2_rn(f0.z, f0.w);
    __half2 h2 = __floats2half2_rn(f1.x, f1.y);
    __half2 h3 = __floats2half2_rn(f1.z, f1.w);
    float2 a0 = __half22float2(h0), a1 = __half22float2(h1);
    float2 a2 = __half22float2(h2), a3 = __half22float2(h3);
    __half2 l0 = __floats2half2_rn(f0.x - a0.x, f0.y - a0.y);
    __half2 l1 = __floats2half2_rn(f0.z - a1.x, f0.w - a1.y);
    __half2 l2 = __floats2half2_rn(f1.x - a2.x, f1.y - a2.y);
    __half2 l3 = __floats2half2_rn(f1.z - a3.x, f1.w - a3.y);
    hi = make_uint4(*(uint32_t*)&h0, *(uint32_t*)&h1, *(uint32_t*)&h2, *(uint32_t*)&h3);
    lo = make_uint4(*(uint32_t*)&l0, *(uint32_t*)&l1, *(uint32_t*)&l2, *(uint32_t*)&l3);
}

// ===========================================================================
// Fused prep kernel: convert_enc (MLP4) | pq | convert_wk | zero
//   [0, 16384)        convert_enc  (4 rows/block)
//   [16384, 16640)    pq
//   [16640, 17152)    convert_wk
//   [17152, 17248)    zero g_weights + ctx
// ===========================================================================
#define PREP_PQ0    16384
#define PREP_WK0    16640
#define PREP_ZERO0  17152
#define PREP_NBLK   17248

__global__ void __launch_bounds__(256)
prep_kernel(const float* __restrict__ enc, const float* __restrict__ q,
            const float* __restrict__ Wq, const float* __restrict__ Wk,
            const int* __restrict__ lengths, float* __restrict__ ctx) {
    __shared__ float q_s[N_B][128];
    int bid = blockIdx.x;
    int tid = threadIdx.x;

    if (bid < PREP_PQ0) {
        // ---- convert_enc: 4 rows (4096 floats = 512 float8) per block ----
        int n  = bid >> 9;
        int t0 = (bid & 511) * 4;
        int lenc = (lengths[n] + 127) & ~127;
        if (t0 >= lenc) return;
        size_t rowbase = ((size_t)n * T_S + t0) * D_E;
        // two float8 units per thread: idx8 = tid, tid+256
        int r0 = tid >> 7, c0 = (tid & 127) * 8;
        int r1 = (tid + 256) >> 7, c1 = ((tid + 256) & 127) * 8;
        size_t b0 = rowbase + (size_t)r0 * D_E + c0;
        size_t b1 = rowbase + (size_t)r1 * D_E + c1;
        // issue all 4 loads first (MLP 4)
        float4 f00 = *(const float4*)(enc + b0);
        float4 f01 = *(const float4*)(enc + b0 + 4);
        float4 f10 = *(const float4*)(enc + b1);
        float4 f11 = *(const float4*)(enc + b1 + 4);
        uint4 hi, lo;
        split8(f00, f01, hi, lo);
        *(uint4*)(g_encH + b0) = hi;
        *(uint4*)(g_encL + b0) = lo;
        split8(f10, f11, hi, lo);
        *(uint4*)(g_encH + b1) = hi;
        *(uint4*)(g_encL + b1) = lo;
    } else if (bid < PREP_WK0) {
        // ---- pq ----
        int b    = bid - PREP_PQ0;          // 0..255
        int half = b & 1;
        int u    = (b >> 1) * 8 + (tid >> 5);
        int lane = tid & 31;
        int k0   = half * 512;

        float acc[N_B];
        #pragma unroll
        for (int n = 0; n < N_B; n++) acc[n] = 0.f;

        for (int kc = 0; kc < 4; kc++) {
            __syncthreads();
            #pragma unroll
            for (int i = 0; i < 4; i++) {
                int flat4 = tid + i * 256;
                int n   = flat4 >> 5;
                int col = (flat4 & 31) * 4;
                *(float4*)&q_s[n][col] =
                    *(const float4*)(q + (size_t)n * D_E + k0 + kc * 128 + col);
            }
            __syncthreads();
            float4 w = *(const float4*)(Wq + (size_t)u * D_E + k0 + kc * 128 + lane * 4);
            #pragma unroll
            for (int n = 0; n < N_B; n++) {
                float4 qv = *(const float4*)&q_s[n][lane * 4];
                acc[n] += qv.x * w.x + qv.y * w.y + qv.z * w.z + qv.w * w.w;
            }
        }
        #pragma unroll
        for (int n = 0; n < N_B; n++) {
            float s = acc[n];
            #pragma unroll
            for (int o = 16; o > 0; o >>= 1) s += __shfl_down_sync(0xffffffffu, s, o);
            if (lane == 0) g_pq[half * N_B * U_D + n * U_D + u] = s;
        }
    } else if (bid < PREP_ZERO0) {
        // ---- convert_wk ----
        size_t base = ((size_t)(bid - PREP_WK0) * 256 + tid) * 8;
        float4 f0 = *(const float4*)(Wk + base);
        float4 f1 = *(const float4*)(Wk + base + 4);
        uint4 hi, lo;
        split8(f0, f1, hi, lo);
        *(uint4*)(g_wkH + base) = hi;
        *(uint4*)(g_wkL + base) = lo;
    } else {
        // ---- zero g_weights (16384 float4) + ctx (8192 float4) ----
        int flat = (bid - PREP_ZERO0) * 256 + tid;   // < 24576
        if (flat < 16384)
            *(float4*)(g_weights + (size_t)flat * 4) = make_float4(0, 0, 0, 0);
        else
            *(float4*)(ctx + (size_t)(flat - 16384) * 4) = make_float4(0, 0, 0, 0);
    }
}

// ===========================================================================
// Fused softmax + context — context reads enc hi halves (half the bytes)
//   grid = (D_E/256, N_B, T_S/128)
// ===========================================================================
__global__ void __launch_bounds__(256)
sm_context_kernel(const int* __restrict__ lengths,
                  float* __restrict__ align, float* __restrict__ ctx) {
    int n    = blockIdx.y;
    int len  = lengths[n];
    int tc   = blockIdx.z * 128;
    bool wr  = (blockIdx.x == 0);
    if (!wr && tc >= len) return;

    int tid = threadIdx.x;
    const float* w = g_weights + (size_t)n * T_S;
    __shared__ float sm[256];

    float m = -1e30f;
    for (int t = tid; t < len; t += 256) m = fmaxf(m, w[t]);
    sm[tid] = m; __syncthreads();
    #pragma unroll
    for (int s = 128; s > 0; s >>= 1) {
        if (tid < s) sm[tid] = fmaxf(sm[tid], sm[tid + s]);
        __syncthreads();
    }
    m = sm[0]; __syncthreads();

    float sum = 0.f;
    for (int t = tid; t < len; t += 256) sum += __expf(w[t] - m);
    sm[tid] = sum; __syncthreads();
    #pragma unroll
    for (int s = 128; s > 0; s >>= 1) {
        if (tid < s) sm[tid] += sm[tid + s];
        __syncthreads();
    }
    float inv = 1.f / sm[0];

    if (wr) {
        if (tid < 128) {
            int t = tc + tid;
            align[(size_t)n * T_S + t] = (t < len) ? __expf(w[t] - m) * inv : 0.f;
        }
        if (tc >= len) return;
    }

    int te = min(tc + 128, len);
    int e  = blockIdx.x * 256 + tid;
    const __half* E = g_encH + ((size_t)n * T_S) * D_E + e;

    float a[8];
    float c0 = 0.f, c1 = 0.f, c2 = 0.f, c3 = 0.f;
    float c4 = 0.f, c5 = 0.f, c6 = 0.f, c7 = 0.f;
    int t = tc;
    for (; t + 8 <= te; t += 8) {
        #pragma unroll
        for (int j = 0; j < 8; j++) a[j] = __expf(w[t + j] - m) * inv;
        c0 += a[0] * __half2float(E[(size_t)(t + 0) * D_E]);
        c1 += a[1] * __half2float(E[(size_t)(t + 1) * D_E]);
        c2 += a[2] * __half2float(E[(size_t)(t + 2) * D_E]);
        c3 += a[3] * __half2float(E[(size_t)(t + 3) * D_E]);
        c4 += a[4] * __half2float(E[(size_t)(t + 4) * D_E]);
        c5 += a[5] * __half2float(E[(size_t)(t + 5) * D_E]);
        c6 += a[6] * __half2float(E[(size_t)(t + 6) * D_E]);
        c7 += a[7] * __half2float(E[(size_t)(t + 7) * D_E]);
    }
    for (; t < te; t++)
        c0 += __expf(w[t] - m) * inv * __half2float(E[(size_t)t * D_E]);
    float tot = ((c0 + c1) + (c2 + c3)) + ((c4 + c5) + (c6 + c7));
    atomicAdd(&ctx[(size_t)n * D_E + e], tot);
}

// ===========================================================================
// mma.sync 3xFP16-split fused logits GEMM — R12 mainloop (cp.async halves)
// ===========================================================================
#define BKF     64                    // fp32 K elems per chunk
#define NKC     (D_E / BKF)           // 16 chunks
#define OFF_AH  0
#define OFF_AL  16384
#define OFF_BH  32768
#define OFF_BL  49152
#define STAGE_B 65536
#define NST     3
#define DYN_SMEM (NST * STAGE_B)

__global__ void __launch_bounds__(512, 1)
weights_tc_kernel(const float* __restrict__ v, const int* __restrict__ lengths) {
    int n  = blockIdx.z;
    int t0 = blockIdx.y * 128;
    int u0 = blockIdx.x * 128;
    int len = lengths[n];
    if (t0 >= len) return;

    extern __shared__ char dyn_smem[];
    __shared__ float wpart[128];
    uint32_t base = smem_u32(dyn_smem);

    int tid  = threadIdx.x;
    int wid  = tid >> 5;
    int lane = tid & 31;
    int mr0 = (wid >> 2) * 32;
    int nc0 = (wid & 3) * 32;

    int rA  = lane & 15;
    int kgA = lane >> 4;
    int swA = rA & 7;
    int rB  = (lane & 7) | ((lane >> 4) << 3);
    int kgB = (lane >> 3) & 1;
    int swB = rB & 7;
    uint32_t rowA = (uint32_t)(mr0 + rA) * 128;
    uint32_t rowB = (uint32_t)(nc0 + rB) * 128;

    int arow = tid >> 2;
    int g0   = (tid & 3) * 2;
    const __half* srcAH = g_encH + ((size_t)n * T_S + t0 + arow) * D_E + g0 * 8;
    const __half* srcAL = g_encL + ((size_t)n * T_S + t0 + arow) * D_E + g0 * 8;
    const __half* srcBH = g_wkH + ((size_t)(u0 + arow)) * D_E + g0 * 8;
    const __half* srcBL = g_wkL + ((size_t)(u0 + arow)) * D_E + g0 * 8;
    uint32_t d0 = base + (uint32_t)arow * 128 + (uint32_t)((g0 ^ (arow & 7)) << 4);
    uint32_t d1 = base + (uint32_t)arow * 128 + (uint32_t)(((g0 + 1) ^ (arow & 7)) << 4);

    float c[2][4][4];
    #pragma unroll
    for (int mi = 0; mi < 2; mi++)
        #pragma unroll
        for (int ni = 0; ni < 4; ni++)
            #pragma unroll
            for (int k = 0; k < 4; k++) c[mi][ni][k] = 0.f;

    uint32_t ah[2][2][4], al[2][2][4], bh[2][8], bl[2][8];

#define CP_STAGE(stg, kchunk) do {                                           \
        uint32_t _st = (uint32_t)(stg) * STAGE_B;                            \
        size_t _ko = (size_t)(kchunk) * BKF;                                 \
        cpasync16(d0 + _st + OFF_AH, srcAH + _ko);                           \
        cpasync16(d1 + _st + OFF_AH, srcAH + _ko + 8);                       \
        cpasync16(d0 + _st + OFF_AL, srcAL + _ko);                           \
        cpasync16(d1 + _st + OFF_AL, srcAL + _ko + 8);                       \
        cpasync16(d0 + _st + OFF_BH, srcBH + _ko);                           \
        cpasync16(d1 + _st + OFF_BH, srcBH + _ko + 8);                       \
        cpasync16(d0 + _st + OFF_BL, srcBL + _ko);                           \
        cpasync16(d1 + _st + OFF_BL, srcBL + _ko + 8);                       \
        cp_commit();                                                         \
    } while (0)

#define LOAD_FRAGS(buf, stg, ks) do {                                        \
        uint32_t _sb = base + (uint32_t)(stg) * STAGE_B;                     \
        uint32_t _gA = (uint32_t)((((ks) * 2 + kgA) ^ swA) << 4);            \
        uint32_t _gB = (uint32_t)((((ks) * 2 + kgB) ^ swB) << 4);            \
        uint32_t _aAH = _sb + OFF_AH + rowA;                                 \
        uint32_t _aAL = _sb + OFF_AL + rowA;                                 \
        uint32_t _aBH = _sb + OFF_BH + rowB;                                 \
        uint32_t _aBL = _sb + OFF_BL + rowB;                                 \
        ldm4(ah[buf][0], _aAH + _gA);                                        \
        ldm4(ah[buf][1], _aAH + 2048 + _gA);                                 \
        ldm4(al[buf][0], _aAL + _gA);                                        \
        ldm4(al[buf][1], _aAL + 2048 + _gA);                                 \
        ldm4(bh[buf] + 0, _aBH + _gB);                                       \
        ldm4(bh[buf] + 4, _aBH + 2048 + _gB);                                \
        ldm4(bl[buf] + 0, _aBL + _gB);                                       \
        ldm4(bl[buf] + 4, _aBL + 2048 + _gB);                                \
    } while (0)

#define MMA_STEP(buf) do {                                                   \
        _Pragma("unroll")                                                    \
        for (int mi = 0; mi < 2; mi++)                                       \
            _Pragma("unroll")                                                \
            for (int ni = 0; ni < 4; ni++) {                                 \
                mma16816(c[mi][ni], ah[buf][mi], bh[buf] + ni * 2);          \
                mma16816(c[mi][ni], ah[buf][mi], bl[buf] + ni * 2);          \
                mma16816(c[mi][ni], al[buf][mi], bh[buf] + ni * 2);          \
            }                                                                \
    } while (0)

    CP_STAGE(0, 0);
    CP_STAGE(1, 1);

    for (int kc = 0; kc < NKC; kc++) {
        asm volatile("cp.async.wait_group 0;" ::: "memory");
        __syncthreads();
        if (kc + 2 < NKC)
            CP_STAGE((kc + 2) % NST, kc + 2);

        int stg = kc % NST;
        if (kc == 0)
            LOAD_FRAGS(0, 0, 0);

        LOAD_FRAGS(1, stg, 1);
        MMA_STEP(0);
        LOAD_FRAGS(0, stg, 2);
        MMA_STEP(1);
        LOAD_FRAGS(1, stg, 3);
        MMA_STEP(0);
        if (kc + 1 < NKC)
            LOAD_FRAGS(0, (kc + 1) % NST, 0);
        MMA_STEP(1);
    }

    // ---- fused epilogue (HW tanh.approx; pq = sum of two k-half partials) ----
    if (tid < 128) wpart[tid] = 0.f;
    __syncthreads();

    float vv[4][2], pqv[4][2];
    {
        const float* pqp = g_pq + (size_t)n * U_D + u0 + nc0;
        const float* vp  = v + u0 + nc0;
        #pragma unroll
        for (int ni = 0; ni < 4; ni++) {
            int cb = ni * 8 + 2 * (lane & 3);
            vv[ni][0] = vp[cb];     vv[ni][1] = vp[cb + 1];
            pqv[ni][0] = pqp[cb] + pqp[N_B * U_D + cb];
            pqv[ni][1] = pqp[cb + 1] + pqp[N_B * U_D + cb + 1];
        }
    }
    #pragma unroll
    for (int mi = 0; mi < 2; mi++) {
        float s1 = 0.f, s2 = 0.f;
        #pragma unroll
        for (int ni = 0; ni < 4; ni++) {
            s1 += vv[ni][0] * tanh_fast(c[mi][ni][0] + pqv[ni][0]);
            s1 += vv[ni][1] * tanh_fast(c[mi][ni][1] + pqv[ni][1]);
            s2 += vv[ni][0] * tanh_fast(c[mi][ni][2] + pqv[ni][0]);
            s2 += vv[ni][1] * tanh_fast(c[mi][ni][3] + pqv[ni][1]);
        }
        s1 += __shfl_xor_sync(0xffffffffu, s1, 1);
        s1 += __shfl_xor_sync(0xffffffffu, s1, 2);
        s2 += __shfl_xor_sync(0xffffffffu, s2, 1);
        s2 += __shfl_xor_sync(0xffffffffu, s2, 2);
        if ((lane & 3) == 0) {
            int r1 = mr0 + mi * 16 + (lane >> 2);
            atomicAdd(&wpart[r1], s1);
            atomicAdd(&wpart[r1 + 8], s2);
        }
    }
    __syncthreads();
    if (tid < 128 && (t0 + tid) < len)
        atomicAdd(&g_weights[n * T_S + t0 + tid], wpart[tid]);
}

// ===========================================================================
extern "C" void kernel_launch(void* const* d_in, const int* in_sizes, int n_in,
                              void* d_out, int out_size) {
    const float* q       = (const float*)d_in[0];  // [32,1,1024]
    const float* enc     = (const float*)d_in[1];  // [32,2048,1024]
    const int*   lengths = (const int*)  d_in[2];  // [32]
    const float* v       = (const float*)d_in[3];  // [1024]
    const float* Wq      = (const float*)d_in[4];  // [1024,1024]
    const float* Wk      = (const float*)d_in[5];  // [1024,1024]

    float* out   = (float*)d_out;
    float* ctx   = out;                 // contexts   [32,1024]
    float* align = out + N_B * D_E;     // alignments [32,2048]

    cudaFuncSetAttribute(weights_tc_kernel,
                         cudaFuncAttributeMaxDynamicSharedMemorySize, DYN_SMEM);

    prep_kernel<<<PREP_NBLK, 256>>>(enc, q, Wq, Wk, lengths, ctx);

    dim3 g(U_D / 128, T_S / 128, N_B);   // u fastest for L2 reuse of enc tiles
    weights_tc_kernel<<<g, 512, DYN_SMEM>>>(v, lengths);

    dim3 gc(D_E / 256, N_B, T_S / 128);
    sm_context_kernel<<<gc, 256>>>(lengths, align, ctx);
}

// round 15
// speedup vs baseline: 1.0447x; 1.0165x over previous
#include <cuda_runtime.h>
#include <cuda_fp16.h>
#include <cstdint>

#define N_B 32
#define T_S 2048
#define D_E 1024
#define U_D 1024

// Scratch (device globals: no allocation allowed)
__device__ float g_pq[2 * N_B * U_D];      // proj_query partials (k halves)
__device__ float g_weights[N_B * T_S];     // logits     [32,2048]
__device__ __half g_encH[N_B * T_S * D_E]; // enc hi fp16 (128MB)
__device__ __half g_encL[N_B * T_S * D_E]; // enc lo fp16 (128MB)
__device__ __half g_wkH[U_D * D_E];        // Wk hi fp16 (2MB)
__device__ __half g_wkL[U_D * D_E];        // Wk lo fp16 (2MB)

// ===========================================================================
// Helpers
// ===========================================================================
__device__ __forceinline__ uint32_t smem_u32(const void* p) {
    uint32_t a;
    asm("{ .reg .u64 t; cvta.to.shared.u64 t, %1; cvt.u32.u64 %0, t; }"
        : "=r"(a) : "l"(p));
    return a;
}
__device__ __forceinline__ void ldm4(uint32_t* r, uint32_t addr) {
    asm volatile("ldmatrix.sync.aligned.m8n8.x4.shared.b16 {%0,%1,%2,%3}, [%4];"
                 : "=r"(r[0]), "=r"(r[1]), "=r"(r[2]), "=r"(r[3]) : "r"(addr));
}
__device__ __forceinline__ void mma16816(float* c, const uint32_t* a,
                                         const uint32_t* b) {
    asm volatile(
        "mma.sync.aligned.m16n8k16.row.col.f32.f16.f16.f32 "
        "{%0,%1,%2,%3}, {%4,%5,%6,%7}, {%8,%9}, {%0,%1,%2,%3};"
        : "+f"(c[0]), "+f"(c[1]), "+f"(c[2]), "+f"(c[3])
        : "r"(a[0]), "r"(a[1]), "r"(a[2]), "r"(a[3]), "r"(b[0]), "r"(b[1]));
}
__device__ __forceinline__ void cpasync16(uint32_t dst, const void* src) {
    asm volatile("cp.async.cg.shared.global [%0], [%1], 16;"
                 :: "r"(dst), "l"(src) : "memory");
}
__device__ __forceinline__ void cp_commit() {
    asm volatile("cp.async.commit_group;" ::: "memory");
}
__device__ __forceinline__ float tanh_fast(float x) {
    float y;
    asm("tanh.approx.f32 %0, %1;" : "=f"(y) : "f"(x));
    return y;
}
__device__ __forceinline__ void split8(const float4 f0, const float4 f1,
                                       uint4& hi, uint4& lo) {
    __half2 h0 = __floats2half2_rn(f0.x, f0.y);
    __half2 h1 = __floats2half2_rn(f0.z, f0.w);
    __half2 h2 = __floats2half2_rn(f1.x, f1.y);
    __half2 h3 = __floats2half2_rn(f1.z, f1.w);
    float2 a0 = __half22float2(h0), a1 = __half22float2(h1);
    float2 a2 = __half22float2(h2), a3 = __half22float2(h3);
    __half2 l0 = __floats2half2_rn(f0.x - a0.x, f0.y - a0.y);
    __half2 l1 = __floats2half2_rn(f0.z - a1.x, f0.w - a1.y);
    __half2 l2 = __floats2half2_rn(f1.x - a2.x, f1.y - a2.y);
    __half2 l3 = __floats2half2_rn(f1.z - a3.x, f1.w - a3.y);
    hi = make_uint4(*(uint32_t*)&h0, *(uint32_t*)&h1, *(uint32_t*)&h2, *(uint32_t*)&h3);
    lo = make_uint4(*(uint32_t*)&l0, *(uint32_t*)&l1, *(uint32_t*)&l2, *(uint32_t*)&l3);
}

// ===========================================================================
// Fused prep kernel: convert_enc (MLP8) | pq | convert_wk | zero
//   [0, 8192)         convert_enc  (8 rows/block, 4 float8/thread)
//   [8192, 8448)      pq
//   [8448, 8960)      convert_wk
//   [8960, 9056)      zero g_weights + ctx
// ===========================================================================
#define PREP_PQ0    8192
#define PREP_WK0    8448
#define PREP_ZERO0  8960
#define PREP_NBLK   9056

__global__ void __launch_bounds__(256)
prep_kernel(const float* __restrict__ enc, const float* __restrict__ q,
            const float* __restrict__ Wq, const float* __restrict__ Wk,
            const int* __restrict__ lengths, float* __restrict__ ctx) {
    __shared__ float q_s[N_B][128];
    int bid = blockIdx.x;
    int tid = threadIdx.x;

    if (bid < PREP_PQ0) {
        // ---- convert_enc: 8 rows (8192 floats = 1024 float8) per block ----
        int n  = bid >> 8;
        int t0 = (bid & 255) * 8;
        int lenc = (lengths[n] + 127) & ~127;
        if (t0 >= lenc) return;
        size_t rowbase = ((size_t)n * T_S + t0) * D_E;
        size_t b[4];
        float4 f[8];
        // issue all 8 loads first (MLP 8)
        #pragma unroll
        for (int i = 0; i < 4; i++) {
            int u8 = tid + i * 256;                 // float8 unit, < 1024
            int r  = u8 >> 7;
            int cc = (u8 & 127) * 8;
            b[i] = rowbase + (size_t)r * D_E + cc;
            f[2 * i]     = *(const float4*)(enc + b[i]);
            f[2 * i + 1] = *(const float4*)(enc + b[i] + 4);
        }
        #pragma unroll
        for (int i = 0; i < 4; i++) {
            uint4 hi, lo;
            split8(f[2 * i], f[2 * i + 1], hi, lo);
            *(uint4*)(g_encH + b[i]) = hi;
            *(uint4*)(g_encL + b[i]) = lo;
        }
    } else if (bid < PREP_WK0) {
        // ---- pq ----
        int bq   = bid - PREP_PQ0;          // 0..255
        int half = bq & 1;
        int u    = (bq >> 1) * 8 + (tid >> 5);
        int lane = tid & 31;
        int k0   = half * 512;

        float acc[N_B];
        #pragma unroll
        for (int n = 0; n < N_B; n++) acc[n] = 0.f;

        for (int kc = 0; kc < 4; kc++) {
            __syncthreads();
            #pragma unroll
            for (int i = 0; i < 4; i++) {
                int flat4 = tid + i * 256;
                int n   = flat4 >> 5;
                int col = (flat4 & 31) * 4;
                *(float4*)&q_s[n][col] =
                    *(const float4*)(q + (size_t)n * D_E + k0 + kc * 128 + col);
            }
            __syncthreads();
            float4 w = *(const float4*)(Wq + (size_t)u * D_E + k0 + kc * 128 + lane * 4);
            #pragma unroll
            for (int n = 0; n < N_B; n++) {
                float4 qv = *(const float4*)&q_s[n][lane * 4];
                acc[n] += qv.x * w.x + qv.y * w.y + qv.z * w.z + qv.w * w.w;
            }
        }
        #pragma unroll
        for (int n = 0; n < N_B; n++) {
            float s = acc[n];
            #pragma unroll
            for (int o = 16; o > 0; o >>= 1) s += __shfl_down_sync(0xffffffffu, s, o);
            if (lane == 0) g_pq[half * N_B * U_D + n * U_D + u] = s;
        }
    } else if (bid < PREP_ZERO0) {
        // ---- convert_wk ----
        size_t base = ((size_t)(bid - PREP_WK0) * 256 + tid) * 8;
        float4 f0 = *(const float4*)(Wk + base);
        float4 f1 = *(const float4*)(Wk + base + 4);
        uint4 hi, lo;
        split8(f0, f1, hi, lo);
        *(uint4*)(g_wkH + base) = hi;
        *(uint4*)(g_wkL + base) = lo;
    } else {
        // ---- zero g_weights (16384 float4) + ctx (8192 float4) ----
        int flat = (bid - PREP_ZERO0) * 256 + tid;   // < 24576
        if (flat < 16384)
            *(float4*)(g_weights + (size_t)flat * 4) = make_float4(0, 0, 0, 0);
        else
            *(float4*)(ctx + (size_t)(flat - 16384) * 4) = make_float4(0, 0, 0, 0);
    }
}

// ===========================================================================
// Fused softmax + context — half2 enc reads, 8-deep t chains
//   grid = (D_E/512, N_B, T_S/128)
// ===========================================================================
__global__ void __launch_bounds__(256)
sm_context_kernel(const int* __restrict__ lengths,
                  float* __restrict__ align, float* __restrict__ ctx) {
    int n    = blockIdx.y;
    int len  = lengths[n];
    int tc   = blockIdx.z * 128;
    bool wr  = (blockIdx.x == 0);
    if (!wr && tc >= len) return;

    int tid = threadIdx.x;
    const float* w = g_weights + (size_t)n * T_S;
    __shared__ float sm[256];

    float m = -1e30f;
    for (int t = tid; t < len; t += 256) m = fmaxf(m, w[t]);
    sm[tid] = m; __syncthreads();
    #pragma unroll
    for (int s = 128; s > 0; s >>= 1) {
        if (tid < s) sm[tid] = fmaxf(sm[tid], sm[tid + s]);
        __syncthreads();
    }
    m = sm[0]; __syncthreads();

    float sum = 0.f;
    for (int t = tid; t < len; t += 256) sum += __expf(w[t] - m);
    sm[tid] = sum; __syncthreads();
    #pragma unroll
    for (int s = 128; s > 0; s >>= 1) {
        if (tid < s) sm[tid] += sm[tid + s];
        __syncthreads();
    }
    float inv = 1.f / sm[0];

    if (wr) {
        if (tid < 128) {
            int t = tc + tid;
            align[(size_t)n * T_S + t] = (t < len) ? __expf(w[t] - m) * inv : 0.f;
        }
        if (tc >= len) return;
    }

    // ---- context: 2 e-columns per thread (half2), 8 t-chains ----
    int te = min(tc + 128, len);
    int e2 = blockIdx.x * 256 + tid;      // half2 index within row
    const __half2* E2 = (const __half2*)(g_encH + ((size_t)n * T_S) * D_E) + e2;

    float a[8];
    float2 c0 = make_float2(0.f, 0.f), c1 = c0, c2 = c0, c3 = c0;
    float2 c4 = c0, c5 = c0, c6 = c0, c7 = c0;
    int t = tc;
    for (; t + 8 <= te; t += 8) {
        #pragma unroll
        for (int j = 0; j < 8; j++) a[j] = __expf(w[t + j] - m) * inv;
        float2 e0 = __half22float2(E2[(size_t)(t + 0) * (D_E / 2)]);
        float2 e1 = __half22float2(E2[(size_t)(t + 1) * (D_E / 2)]);
        float2 e2v = __half22float2(E2[(size_t)(t + 2) * (D_E / 2)]);
        float2 e3 = __half22float2(E2[(size_t)(t + 3) * (D_E / 2)]);
        float2 e4 = __half22float2(E2[(size_t)(t + 4) * (D_E / 2)]);
        float2 e5 = __half22float2(E2[(size_t)(t + 5) * (D_E / 2)]);
        float2 e6 = __half22float2(E2[(size_t)(t + 6) * (D_E / 2)]);
        float2 e7 = __half22float2(E2[(size_t)(t + 7) * (D_E / 2)]);
        c0.x += a[0] * e0.x; c0.y += a[0] * e0.y;
        c1.x += a[1] * e1.x; c1.y += a[1] * e1.y;
        c2.x += a[2] * e2v.x; c2.y += a[2] * e2v.y;
        c3.x += a[3] * e3.x; c3.y += a[3] * e3.y;
        c4.x += a[4] * e4.x; c4.y += a[4] * e4.y;
        c5.x += a[5] * e5.x; c5.y += a[5] * e5.y;
        c6.x += a[6] * e6.x; c6.y += a[6] * e6.y;
        c7.x += a[7] * e7.x; c7.y += a[7] * e7.y;
    }
    for (; t < te; t++) {
        float av = __expf(w[t] - m) * inv;
        float2 ev = __half22float2(E2[(size_t)t * (D_E / 2)]);
        c0.x += av * ev.x; c0.y += av * ev.y;
    }
    float totx = ((c0.x + c1.x) + (c2.x + c3.x)) + ((c4.x + c5.x) + (c6.x + c7.x));
    float toty = ((c0.y + c1.y) + (c2.y + c3.y)) + ((c4.y + c5.y) + (c6.y + c7.y));
    float* cp = &ctx[(size_t)n * D_E + e2 * 2];
    atomicAdd(cp, totx);
    atomicAdd(cp + 1, toty);
}

// ===========================================================================
// mma.sync 3xFP16-split fused logits GEMM — R12 mainloop (cp.async halves)
// ===========================================================================
#define BKF     64                    // fp32 K elems per chunk
#define NKC     (D_E / BKF)           // 16 chunks
#define OFF_AH  0
#define OFF_AL  16384
#define OFF_BH  32768
#define OFF_BL  49152
#define STAGE_B 65536
#define NST     3
#define DYN_SMEM (NST * STAGE_B)

__global__ void __launch_bounds__(512, 1)
weights_tc_kernel(const float* __restrict__ v, const int* __restrict__ lengths) {
    int n  = blockIdx.z;
    int t0 = blockIdx.y * 128;
    int u0 = blockIdx.x * 128;
    int len = lengths[n];
    if (t0 >= len) return;

    extern __shared__ char dyn_smem[];
    __shared__ float wpart[128];
    uint32_t base = smem_u32(dyn_smem);

    int tid  = threadIdx.x;
    int wid  = tid >> 5;
    int lane = tid & 31;
    int mr0 = (wid >> 2) * 32;
    int nc0 = (wid & 3) * 32;

    int rA  = lane & 15;
    int kgA = lane >> 4;
    int swA = rA & 7;
    int rB  = (lane & 7) | ((lane >> 4) << 3);
    int kgB = (lane >> 3) & 1;
    int swB = rB & 7;
    uint32_t rowA = (uint32_t)(mr0 + rA) * 128;
    uint32_t rowB = (uint32_t)(nc0 + rB) * 128;

    int arow = tid >> 2;
    int g0   = (tid & 3) * 2;
    const __half* srcAH = g_encH + ((size_t)n * T_S + t0 + arow) * D_E + g0 * 8;
    const __half* srcAL = g_encL + ((size_t)n * T_S + t0 + arow) * D_E + g0 * 8;
    const __half* srcBH = g_wkH + ((size_t)(u0 + arow)) * D_E + g0 * 8;
    const __half* srcBL = g_wkL + ((size_t)(u0 + arow)) * D_E + g0 * 8;
    uint32_t d0 = base + (uint32_t)arow * 128 + (uint32_t)((g0 ^ (arow & 7)) << 4);
    uint32_t d1 = base + (uint32_t)arow * 128 + (uint32_t)(((g0 + 1) ^ (arow & 7)) << 4);

    float c[2][4][4];
    #pragma unroll
    for (int mi = 0; mi < 2; mi++)
        #pragma unroll
        for (int ni = 0; ni < 4; ni++)
            #pragma unroll
            for (int k = 0; k < 4; k++) c[mi][ni][k] = 0.f;

    uint32_t ah[2][2][4], al[2][2][4], bh[2][8], bl[2][8];

#define CP_STAGE(stg, kchunk) do {                                           \
        uint32_t _st = (uint32_t)(stg) * STAGE_B;                            \
        size_t _ko = (size_t)(kchunk) * BKF;                                 \
        cpasync16(d0 + _st + OFF_AH, srcAH + _ko);                           \
        cpasync16(d1 + _st + OFF_AH, srcAH + _ko + 8);                       \
        cpasync16(d0 + _st + OFF_AL, srcAL + _ko);                           \
        cpasync16(d1 + _st + OFF_AL, srcAL + _ko + 8);                       \
        cpasync16(d0 + _st + OFF_BH, srcBH + _ko);                           \
        cpasync16(d1 + _st + OFF_BH, srcBH + _ko + 8);                       \
        cpasync16(d0 + _st + OFF_BL, srcBL + _ko);                           \
        cpasync16(d1 + _st + OFF_BL, srcBL + _ko + 8);                       \
        cp_commit();                                                         \
    } while (0)

#define LOAD_FRAGS(buf, stg, ks) do {                                        \
        uint32_t _sb = base + (uint32_t)(stg) * STAGE_B;                     \
        uint32_t _gA = (uint32_t)((((ks) * 2 + kgA) ^ swA) << 4);            \
        uint32_t _gB = (uint32_t)((((ks) * 2 + kgB) ^ swB) << 4);            \
        uint32_t _aAH = _sb + OFF_AH + rowA;                                 \
        uint32_t _aAL = _sb + OFF_AL + rowA;                                 \
        uint32_t _aBH = _sb + OFF_BH + rowB;                                 \
        uint32_t _aBL = _sb + OFF_BL + rowB;                                 \
        ldm4(ah[buf][0], _aAH + _gA);                                        \
        ldm4(ah[buf][1], _aAH + 2048 + _gA);                                 \
        ldm4(al[buf][0], _aAL + _gA);                                        \
        ldm4(al[buf][1], _aAL + 2048 + _gA);                                 \
        ldm4(bh[buf] + 0, _aBH + _gB);                                       \
        ldm4(bh[buf] + 4, _aBH + 2048 + _gB);                                \
        ldm4(bl[buf] + 0, _aBL + _gB);                                       \
        ldm4(bl[buf] + 4, _aBL + 2048 + _gB);                                \
    } while (0)

#define MMA_STEP(buf) do {                                                   \
        _Pragma("unroll")                                                    \
        for (int mi = 0; mi < 2; mi++)                                       \
            _Pragma("unroll")                                                \
            for (int ni = 0; ni < 4; ni++) {                                 \
                mma16816(c[mi][ni], ah[buf][mi], bh[buf] + ni * 2);          \
                mma16816(c[mi][ni], ah[buf][mi], bl[buf] + ni * 2);          \
                mma16816(c[mi][ni], al[buf][mi], bh[buf] + ni * 2);          \
            }                                                                \
    } while (0)

    CP_STAGE(0, 0);
    CP_STAGE(1, 1);

    for (int kc = 0; kc < NKC; kc++) {
        asm volatile("cp.async.wait_group 0;" ::: "memory");
        __syncthreads();
        if (kc + 2 < NKC)
            CP_STAGE((kc + 2) % NST, kc + 2);

        int stg = kc % NST;
        if (kc == 0)
            LOAD_FRAGS(0, 0, 0);

        LOAD_FRAGS(1, stg, 1);
        MMA_STEP(0);
        LOAD_FRAGS(0, stg, 2);
        MMA_STEP(1);
        LOAD_FRAGS(1, stg, 3);
        MMA_STEP(0);
        if (kc + 1 < NKC)
            LOAD_FRAGS(0, (kc + 1) % NST, 0);
        MMA_STEP(1);
    }

    // ---- fused epilogue (HW tanh.approx; pq = sum of two k-half partials) ----
    if (tid < 128) wpart[tid] = 0.f;
    __syncthreads();

    float vv[4][2], pqv[4][2];
    {
        const float* pqp = g_pq + (size_t)n * U_D + u0 + nc0;
        const float* vp  = v + u0 + nc0;
        #pragma unroll
        for (int ni = 0; ni < 4; ni++) {
            int cb = ni * 8 + 2 * (lane & 3);
            vv[ni][0] = vp[cb];     vv[ni][1] = vp[cb + 1];
            pqv[ni][0] = pqp[cb] + pqp[N_B * U_D + cb];
            pqv[ni][1] = pqp[cb + 1] + pqp[N_B * U_D + cb + 1];
        }
    }
    #pragma unroll
    for (int mi = 0; mi < 2; mi++) {
        float s1 = 0.f, s2 = 0.f;
        #pragma unroll
        for (int ni = 0; ni < 4; ni++) {
            s1 += vv[ni][0] * tanh_fast(c[mi][ni][0] + pqv[ni][0]);
            s1 += vv[ni][1] * tanh_fast(c[mi][ni][1] + pqv[ni][1]);
            s2 += vv[ni][0] * tanh_fast(c[mi][ni][2] + pqv[ni][0]);
            s2 += vv[ni][1] * tanh_fast(c[mi][ni][3] + pqv[ni][1]);
        }
        s1 += __shfl_xor_sync(0xffffffffu, s1, 1);
        s1 += __shfl_xor_sync(0xffffffffu, s1, 2);
        s2 += __shfl_xor_sync(0xffffffffu, s2, 1);
        s2 += __shfl_xor_sync(0xffffffffu, s2, 2);
        if ((lane & 3) == 0) {
            int r1 = mr0 + mi * 16 + (lane >> 2);
            atomicAdd(&wpart[r1], s1);
            atomicAdd(&wpart[r1 + 8], s2);
        }
    }
    __syncthreads();
    if (tid < 128 && (t0 + tid) < len)
        atomicAdd(&g_weights[n * T_S + t0 + tid], wpart[tid]);
}

// ===========================================================================
extern "C" void kernel_launch(void* const* d_in, const int* in_sizes, int n_in,
                              void* d_out, int out_size) {
    const float* q       = (const float*)d_in[0];  // [32,1,1024]
    const float* enc     = (const float*)d_in[1];  // [32,2048,1024]
    const int*   lengths = (const int*)  d_in[2];  // [32]
    const float* v       = (const float*)d_in[3];  // [1024]
    const float* Wq      = (const float*)d_in[4];  // [1024,1024]
    const float* Wk      = (const float*)d_in[5];  // [1024,1024]

    float* out   = (float*)d_out;
    float* ctx   = out;                 // contexts   [32,1024]
    float* align = out + N_B * D_E;     // alignments [32,2048]

    cudaFuncSetAttribute(weights_tc_kernel,
                         cudaFuncAttributeMaxDynamicSharedMemorySize, DYN_SMEM);

    prep_kernel<<<PREP_NBLK, 256>>>(enc, q, Wq, Wk, lengths, ctx);

    dim3 g(U_D / 128, T_S / 128, N_B);   // u fastest for L2 reuse of enc tiles
    weights_tc_kernel<<<g, 512, DYN_SMEM>>>(v, lengths);

    dim3 gc(D_E / 512, N_B, T_S / 128);
    sm_context_kernel<<<gc, 256>>>(lengths, align, ctx);
}